// round 11
// baseline (speedup 1.0000x reference)
#include <cuda_runtime.h>
#include <cuda_fp16.h>
#include <cstdint>
#include <math.h>

// ---------------------------------------------------------------------------
// Problem constants
// ---------------------------------------------------------------------------
#define BATCH 4
#define SEQ   2048
#define FDIM  1024
#define DKDIM 1024

// ---------------------------------------------------------------------------
// fp16 mma.sync GEMM tiling: CTA 128x128, warp 64x32, BK=64, 3 stages, 2 CTA/SM
// ---------------------------------------------------------------------------
#define BM 128
#define BN 128
#define BK 64
#define STAGES 3
#define GEMM_THREADS 256

#define ROWH 72
#define A_STAGE_HALVES (BM * ROWH)
#define B_STAGE_HALVES (BN * ROWH)
#define STAGE_HALVES   (A_STAGE_HALVES + B_STAGE_HALVES)
#define GEMM_SMEM      (STAGES * STAGE_HALVES * 2)   // 110,592 B

#define VSCALE 64.0f
#define MTILES (SEQ / BM)

// ---------------------------------------------------------------------------
// Scratch (device globals — no dynamic allocation allowed)
// ---------------------------------------------------------------------------
__device__ __half g_xh  [(size_t)BATCH * SEQ * FDIM];
__device__ __half g_gA  [(size_t)2 * FDIM * DKDIM];          // slot0: Wk, slot1: Wo^T
__device__ __half g_gB  [(size_t)2 * FDIM * DKDIM];          // slot0: Wq, slot1: Wv
__device__ __half g_mb  [(size_t)2 * DKDIM * FDIM];          // slot0: M'=WkWq^T, slot1: W'^T
__device__ __half g_qv  [(size_t)BATCH * SEQ * 2 * DKDIM];   // [qm | vw] in N
__device__ __half g_vwt [(size_t)BATCH * FDIM * SEQ];        // scaled vw^T per batch
__device__ __half g_sc  [(size_t)BATCH * SEQ * SEQ];         // exp(scores)
__device__ float  g_bias2[(size_t)2 * DKDIM];                // 0 | b'=bv@Wo
__device__ float  g_w1  [FDIM];                              // Wq @ bk
__device__ float  g_w2  [FDIM];                              // Wk @ bq
__device__ float  g_c   [1];                                 // bq . bk
__device__ float  g_u   [(size_t)BATCH * SEQ];               // x.w1 + c
__device__ float  g_v   [(size_t)BATCH * SEQ];               // x.w2
__device__ float  g_part[(size_t)BATCH * MTILES * SEQ];

// ---------------------------------------------------------------------------
// Helpers
// ---------------------------------------------------------------------------
__device__ __forceinline__ uint32_t smem_u32(const void* p) {
    uint32_t a;
    asm("{ .reg .u64 t; cvta.to.shared.u64 t, %1; cvt.u32.u64 %0, t; }" : "=r"(a) : "l"(p));
    return a;
}
__device__ __forceinline__ void cp_async16(uint32_t dst, const void* src) {
    asm volatile("cp.async.cg.shared.global [%0], [%1], 16;" :: "r"(dst), "l"(src) : "memory");
}
__device__ __forceinline__ void cp_commit() {
    asm volatile("cp.async.commit_group;" ::: "memory");
}
__device__ __forceinline__ void cp_wait_1() {
    asm volatile("cp.async.wait_group 1;" ::: "memory");
}
__device__ __forceinline__ void ldmatrix_x4(uint32_t* r, uint32_t addr) {
    asm volatile("ldmatrix.sync.aligned.m8n8.x4.shared.b16 {%0,%1,%2,%3}, [%4];"
                 : "=r"(r[0]), "=r"(r[1]), "=r"(r[2]), "=r"(r[3]) : "r"(addr));
}
__device__ __forceinline__ void mma_f16(float* d, const uint32_t* a,
                                        uint32_t b0, uint32_t b1) {
    asm volatile(
        "mma.sync.aligned.m16n8k16.row.col.f32.f16.f16.f32 "
        "{%0,%1,%2,%3}, {%4,%5,%6,%7}, {%8,%9}, {%0,%1,%2,%3};"
        : "+f"(d[0]), "+f"(d[1]), "+f"(d[2]), "+f"(d[3])
        : "r"(a[0]), "r"(a[1]), "r"(a[2]), "r"(a[3]), "r"(b0), "r"(b1));
}

// ---------------------------------------------------------------------------
// fp16 tensor-core GEMM:  C = op(alpha * A * B^T + bias)
//   mode 0: plain; mode 1: C = exp((acc + u_m + v_n) * alpha), col sums -> part
// ---------------------------------------------------------------------------
__global__ void __launch_bounds__(GEMM_THREADS, 2)
gemm_f16_kernel(const __half* __restrict__ A, const __half* __restrict__ B,
                const float* __restrict__ bias, void* __restrict__ Cv,
                float* __restrict__ part,
                const float* __restrict__ upt, const float* __restrict__ vpt,
                int M, int N, int K, int lda, int ldb, int ldc,
                long long sA, long long sB, long long sC,
                float alpha, int c_half, int mode)
{
    extern __shared__ __half sm[];
    __shared__ float csum[2][BN];
    const int tid = threadIdx.x;
    const int wid = tid >> 5;
    const int lane = tid & 31;
    const int g   = lane >> 2;
    const int tig = lane & 3;
    const int mw = (wid & 1) * 64;
    const int nw = (wid >> 1) * 32;

    A += (long long)blockIdx.z * sA;
    B += (long long)blockIdx.z * sB;
    const int m0 = blockIdx.y * BM;
    const int n0 = blockIdx.x * BN;

    float acc[4][4][4];
#pragma unroll
    for (int mt = 0; mt < 4; mt++)
#pragma unroll
        for (int nt = 0; nt < 4; nt++)
#pragma unroll
            for (int r = 0; r < 4; r++) acc[mt][nt][r] = 0.0f;

    const uint32_t sm_base = smem_u32(sm);
    const int KT = K / BK;

    auto load_stage = [&](int p) {
        const uint32_t base = sm_base + (uint32_t)((p % STAGES) * STAGE_HALVES) * 2u;
        const uint32_t bbase = base + A_STAGE_HALVES * 2u;
        const int k0 = p * BK;
#pragma unroll
        for (int t = 0; t < 4; t++) {
            int c = tid + t * GEMM_THREADS;
            int r = c >> 3, kc = c & 7;
            cp_async16(base + (uint32_t)(r * ROWH + kc * 8) * 2u,
                       A + (long long)(m0 + r) * lda + k0 + kc * 8);
        }
#pragma unroll
        for (int t = 0; t < 4; t++) {
            int c = tid + t * GEMM_THREADS;
            int r = c >> 3, kc = c & 7;
            cp_async16(bbase + (uint32_t)(r * ROWH + kc * 8) * 2u,
                       B + (long long)(n0 + r) * ldb + k0 + kc * 8);
        }
    };

    load_stage(0); cp_commit();
    load_stage(1); cp_commit();

    const int row_a  = ((lane >> 3) & 1) * 8 + (lane & 7);
    const int kadd_a = ((lane >> 4) & 1) * 8;
    const int row_b  = ((lane >> 4) & 1) * 8 + (lane & 7);
    const int kadd_b = ((lane >> 3) & 1) * 8;

    for (int kt = 0; kt < KT; kt++) {
        cp_wait_1();
        __syncthreads();

        if (kt + 2 < KT) load_stage(kt + 2);
        cp_commit();

        const uint32_t sa  = sm_base + (uint32_t)((kt % STAGES) * STAGE_HALVES) * 2u;
        const uint32_t sbp = sa + A_STAGE_HALVES * 2u;
#pragma unroll
        for (int kk = 0; kk < 4; kk++) {
            const int k16 = kk * 16;
            uint32_t a[4][4], b[2][4];
#pragma unroll
            for (int mt = 0; mt < 4; mt++)
                ldmatrix_x4(a[mt],
                    sa + (uint32_t)((mw + mt * 16 + row_a) * ROWH + k16 + kadd_a) * 2u);
#pragma unroll
            for (int i = 0; i < 2; i++)
                ldmatrix_x4(b[i],
                    sbp + (uint32_t)((nw + i * 16 + row_b) * ROWH + k16 + kadd_b) * 2u);
#pragma unroll
            for (int mt = 0; mt < 4; mt++)
#pragma unroll
                for (int nt = 0; nt < 4; nt++)
                    mma_f16(acc[mt][nt], a[mt],
                            b[nt >> 1][(nt & 1) * 2], b[nt >> 1][(nt & 1) * 2 + 1]);
        }
    }

    if (mode == 1) {
        // ---- exp((acc + u_m + v_n) * alpha) epilogue + column partial sums ----
        __half* C = (__half*)Cv + (long long)blockIdx.z * sC;
        const float* u_ = upt + (long long)blockIdx.z * SEQ;
        const float* v_ = vpt + (long long)blockIdx.z * SEQ;
        float vn0[4], vn1[4];
#pragma unroll
        for (int nt = 0; nt < 4; nt++) {
            const int n = n0 + nw + nt * 8 + 2 * tig;
            vn0[nt] = v_[n];
            vn1[nt] = v_[n + 1];
        }
        float cs0[4], cs1[4];
#pragma unroll
        for (int nt = 0; nt < 4; nt++) { cs0[nt] = 0.0f; cs1[nt] = 0.0f; }
#pragma unroll
        for (int mt = 0; mt < 4; mt++) {
            const int m = m0 + mw + mt * 16 + g;
            const float um0 = u_[m], um8 = u_[m + 8];
#pragma unroll
            for (int nt = 0; nt < 4; nt++) {
                const int n = n0 + nw + nt * 8 + 2 * tig;
                float e0 = __expf((acc[mt][nt][0] + um0 + vn0[nt]) * alpha);
                float e1 = __expf((acc[mt][nt][1] + um0 + vn1[nt]) * alpha);
                float e2 = __expf((acc[mt][nt][2] + um8 + vn0[nt]) * alpha);
                float e3 = __expf((acc[mt][nt][3] + um8 + vn1[nt]) * alpha);
                cs0[nt] += e0 + e2;
                cs1[nt] += e1 + e3;
                *(__half2*)(C + (long long)m * ldc + n)       = __floats2half2_rn(e0, e1);
                *(__half2*)(C + (long long)(m + 8) * ldc + n) = __floats2half2_rn(e2, e3);
            }
        }
#pragma unroll
        for (int msk = 4; msk <= 16; msk <<= 1) {
#pragma unroll
            for (int nt = 0; nt < 4; nt++) {
                cs0[nt] += __shfl_xor_sync(0xffffffffu, cs0[nt], msk);
                cs1[nt] += __shfl_xor_sync(0xffffffffu, cs1[nt], msk);
            }
        }
        if (g == 0) {
#pragma unroll
            for (int nt = 0; nt < 4; nt++) {
                csum[wid & 1][nw + nt * 8 + 2 * tig]     = cs0[nt];
                csum[wid & 1][nw + nt * 8 + 2 * tig + 1] = cs1[nt];
            }
        }
        __syncthreads();
        if (tid < BN)
            part[((long long)blockIdx.z * MTILES + blockIdx.y) * SEQ + n0 + tid] =
                csum[0][tid] + csum[1][tid];
        return;
    }

    // ---- plain epilogue ----
#pragma unroll
    for (int mt = 0; mt < 4; mt++) {
        const int m = m0 + mw + mt * 16 + g;
#pragma unroll
        for (int nt = 0; nt < 4; nt++) {
            const int n = n0 + nw + nt * 8 + 2 * tig;
            float2 v0, v1;
            v0.x = acc[mt][nt][0] * alpha;
            v0.y = acc[mt][nt][1] * alpha;
            v1.x = acc[mt][nt][2] * alpha;
            v1.y = acc[mt][nt][3] * alpha;
            if (bias) {
                float bx = bias[n], by = bias[n + 1];
                v0.x += bx; v0.y += by;
                v1.x += bx; v1.y += by;
            }
            if (c_half) {
                __half* C = (__half*)Cv + (long long)blockIdx.z * sC;
                *(__half2*)(C + (long long)m * ldc + n)       = __floats2half2_rn(v0.x, v0.y);
                *(__half2*)(C + (long long)(m + 8) * ldc + n) = __floats2half2_rn(v1.x, v1.y);
            } else {
                float* C = (float*)Cv + (long long)blockIdx.z * sC;
                *(float2*)(C + (long long)m * ldc + n)       = v0;
                *(float2*)(C + (long long)(m + 8) * ldc + n) = v1;
            }
        }
    }
}

// ---------------------------------------------------------------------------
// Fused prep. 1D grid dispatch (256 threads each):
// [0,8192)        x f2h
// [8192,9216)     Wq f2h -> gB slot0
// [9216,10240)    Wk f2h -> gA slot0
// [10240,11264)   Wv f2h -> gB slot1
// [11264,12288)   Wo transpose -> gA slot1 (Wo^T)
// [12288,12416)   w1 = Wq@bk   (warp per row, coalesced)
// [12416,12544)   w2 = Wk@bq   (warp per row, coalesced)
// [12544,12548)   b' = bv@Wo -> bias2[1024:2048]  (coalesced over f)
// [12548,12552)   bias2[0:1024] = 0
// [12552]         c = bq.bk
// ---------------------------------------------------------------------------
__global__ void __launch_bounds__(256)
prep_kernel(const float* __restrict__ x,
            const float* __restrict__ Wq, const float* __restrict__ Wk,
            const float* __restrict__ Wv, const float* __restrict__ Wo,
            const float* __restrict__ bq, const float* __restrict__ bk,
            const float* __restrict__ bv,
            __half* __restrict__ xh, __half* __restrict__ gA,
            __half* __restrict__ gB, float* __restrict__ bias2,
            float* __restrict__ w1, float* __restrict__ w2,
            float* __restrict__ cc)
{
    __shared__ float t[32][33];
    const int b = blockIdx.x;
    const int tid = threadIdx.x;
    const int tx = tid & 31, ty = tid >> 5;

    if (b < 8192) {
        size_t i = (size_t)b * 256 + tid;
        float4 v = ((const float4*)x)[i];
        ((__half2*)xh)[2 * i]     = __floats2half2_rn(v.x, v.y);
        ((__half2*)xh)[2 * i + 1] = __floats2half2_rn(v.z, v.w);
    } else if (b < 11264) {
        const int z = (b - 8192) >> 10;                 // 0: Wq, 1: Wk, 2: Wv
        const float* in = (z == 0) ? Wq : (z == 1) ? Wk : Wv;
        __half* o = (z == 0) ? gB : (z == 1) ? gA : (gB + (size_t)FDIM * DKDIM);
        size_t i = (size_t)((b - 8192) & 1023) * 256 + tid;
        float4 v = ((const float4*)in)[i];
        ((__half2*)o)[2 * i]     = __floats2half2_rn(v.x, v.y);
        ((__half2*)o)[2 * i + 1] = __floats2half2_rn(v.z, v.w);
    } else if (b < 12288) {
        // Wo [DK,F] -> Wo^T [F,DK] into gA slot1
        const int tt = b - 11264;
        const int by = tt >> 5, bx = tt & 31;
        const int c0 = bx * 32, r0 = by * 32;
        __half* o = gA + (size_t)FDIM * DKDIM;
#pragma unroll
        for (int i = 0; i < 32; i += 8)
            t[ty + i][tx] = Wo[(long long)(r0 + ty + i) * FDIM + c0 + tx];
        __syncthreads();
#pragma unroll
        for (int i = 0; i < 32; i += 8)
            o[(long long)(c0 + ty + i) * DKDIM + r0 + tx] =
                __float2half_rn(t[tx][ty + i]);
    } else if (b < 12544) {
        // w1 / w2: one warp per output row, lanes over d (coalesced)
        const int is_w2 = (b >= 12416);
        const int f = ((b - (is_w2 ? 12416 : 12288)) << 3) + ty;   // 8 warps/block
        const float* row = (is_w2 ? Wk : Wq) + (long long)f * DKDIM;
        const float* bb = is_w2 ? bq : bk;
        float s = 0.0f;
#pragma unroll
        for (int j = 0; j < DKDIM / 32; j++)
            s += row[tx + j * 32] * bb[tx + j * 32];
#pragma unroll
        for (int msk = 16; msk > 0; msk >>= 1)
            s += __shfl_xor_sync(0xffffffffu, s, msk);
        if (tx == 0) (is_w2 ? w2 : w1)[f] = s;
    } else if (b < 12548) {
        // b'[f] = sum_d bv[d] * Wo[d,f]  (threads f consecutive -> coalesced)
        const int f = (b - 12544) * 256 + tid;
        float s = 0.0f;
        for (int d = 0; d < DKDIM; d++) s += bv[d] * Wo[(long long)d * FDIM + f];
        bias2[DKDIM + f] = s;
    } else if (b < 12552) {
        bias2[(b - 12548) * 256 + tid] = 0.0f;
    } else {
        __shared__ float red[256];
        float s = 0.0f;
        for (int d = tid; d < DKDIM; d += 256) s += bq[d] * bk[d];
        red[tid] = s;
        __syncthreads();
        for (int off = 128; off > 0; off >>= 1) {
            if (tid < off) red[tid] += red[tid + off];
            __syncthreads();
        }
        if (tid == 0) cc[0] = red[0];
    }
}

// ---------------------------------------------------------------------------
// u[i] = x[i].w1 + c ; v[i] = x[i].w2   (one warp per row)
// ---------------------------------------------------------------------------
__global__ void __launch_bounds__(256)
uv_kernel(const float* __restrict__ x, const float* __restrict__ w1,
          const float* __restrict__ w2, const float* __restrict__ cc,
          float* __restrict__ u, float* __restrict__ v)
{
    const int lane = threadIdx.x & 31;
    const int w = threadIdx.x >> 5;
    const long long i = (long long)blockIdx.x * 8 + w;
    const float* row = x + i * FDIM;
    float s1 = 0.0f, s2 = 0.0f;
#pragma unroll
    for (int j = 0; j < FDIM / 32; j++) {
        float xv = row[lane + j * 32];
        s1 += xv * w1[lane + j * 32];
        s2 += xv * w2[lane + j * 32];
    }
#pragma unroll
    for (int msk = 16; msk > 0; msk >>= 1) {
        s1 += __shfl_xor_sync(0xffffffffu, s1, msk);
        s2 += __shfl_xor_sync(0xffffffffu, s2, msk);
    }
    if (lane == 0) { u[i] = s1 + cc[0]; v[i] = s2; }
}

// ---------------------------------------------------------------------------
// vw^T with softmax normalization folded in (colsum reduced inline from part)
// out[f, k] = vw[k, f] * VSCALE / colsum[b, k]
// ---------------------------------------------------------------------------
__global__ void __launch_bounds__(256)
transpose_scale_kernel(const __half* __restrict__ in, __half* __restrict__ out,
                       const float* __restrict__ part,
                       int R, int C, int ldIn, long long sIn, long long sOut)
{
    __shared__ __half t[32][34];
    in  += (long long)blockIdx.z * sIn;
    out += (long long)blockIdx.z * sOut;
    const int c0 = blockIdx.x * 32, r0 = blockIdx.y * 32;
#pragma unroll
    for (int i = 0; i < 32; i += 8)
        t[threadIdx.y + i][threadIdx.x] =
            in[(long long)(r0 + threadIdx.y + i) * ldIn + c0 + threadIdx.x];
    __syncthreads();
    const float* pp = part + (long long)blockIdx.z * MTILES * SEQ + r0 + threadIdx.x;
    float s = 0.0f;
#pragma unroll
    for (int tt = 0; tt < MTILES; tt++) s += pp[(long long)tt * SEQ];
    const float inv = VSCALE / s;
#pragma unroll
    for (int i = 0; i < 32; i += 8)
        out[(long long)(c0 + threadIdx.y + i) * R + r0 + threadIdx.x] =
            __float2half_rn(__half2float(t[threadIdx.x][threadIdx.y + i]) * inv);
}

// ---------------------------------------------------------------------------
// Launcher
// ---------------------------------------------------------------------------
extern "C" void kernel_launch(void* const* d_in, const int* in_sizes, int n_in,
                              void* d_out, int out_size)
{
    const float* x  = (const float*)d_in[0];
    const float* Wq = (const float*)d_in[1];
    const float* bq = (const float*)d_in[2];
    const float* Wk = (const float*)d_in[3];
    const float* bk = (const float*)d_in[4];
    const float* Wv = (const float*)d_in[5];
    const float* bv = (const float*)d_in[6];
    const float* Wo = (const float*)d_in[7];
    const float* bo = (const float*)d_in[8];
    float* out = (float*)d_out;

    __half *xh, *gA, *gB, *mb, *qv, *vwt, *sc;
    float *bias2, *w1, *w2, *cc, *u, *v, *part;
    cudaGetSymbolAddress((void**)&xh,    g_xh);
    cudaGetSymbolAddress((void**)&gA,    g_gA);
    cudaGetSymbolAddress((void**)&gB,    g_gB);
    cudaGetSymbolAddress((void**)&mb,    g_mb);
    cudaGetSymbolAddress((void**)&qv,    g_qv);
    cudaGetSymbolAddress((void**)&vwt,   g_vwt);
    cudaGetSymbolAddress((void**)&sc,    g_sc);
    cudaGetSymbolAddress((void**)&bias2, g_bias2);
    cudaGetSymbolAddress((void**)&w1,    g_w1);
    cudaGetSymbolAddress((void**)&w2,    g_w2);
    cudaGetSymbolAddress((void**)&cc,    g_c);
    cudaGetSymbolAddress((void**)&u,     g_u);
    cudaGetSymbolAddress((void**)&v,     g_v);
    cudaGetSymbolAddress((void**)&part,  g_part);

    cudaFuncSetAttribute(gemm_f16_kernel,
                         cudaFuncAttributeMaxDynamicSharedMemorySize, GEMM_SMEM);

    const int MS = BATCH * SEQ;                        // 8192
    const int N2 = 2 * DKDIM;                          // 2048
    const long long sQV = (long long)SEQ * N2;
    const long long sXF = (long long)SEQ * FDIM;
    const long long sSS = (long long)SEQ * SEQ;
    const long long sW  = (long long)FDIM * DKDIM;
    const float inv_sqrt_dk = 1.0f / 32.0f;

    // 0) fused prep (all coalesced)
    prep_kernel<<<12553, 256>>>(x, Wq, Wk, Wv, Wo, bq, bk, bv,
                                xh, gA, gB, bias2, w1, w2, cc);

    // 0b) batched prep GEMM: z=0: M' = Wk@Wq^T ; z=1: W'^T = Wo^T@Wv^T
    {
        dim3 grd(FDIM / BN, FDIM / BM, 2);
        gemm_f16_kernel<<<grd, GEMM_THREADS, GEMM_SMEM>>>(
            gA, gB, nullptr, mb, nullptr, nullptr, nullptr,
            FDIM, FDIM, DKDIM, DKDIM, DKDIM, FDIM, sW, sW, sW, 1.0f, 1, 0);
    }

    // 0c) u, v rank-1 score terms
    uv_kernel<<<MS / 8, 256>>>(x, w1, w2, cc, u, v);

    // 1) fused [qm | vw] = xh @ [M' | W'^T]^T + [0 | b']  (half out)
    {
        dim3 grd(N2 / BN, MS / BM, 1);
        gemm_f16_kernel<<<grd, GEMM_THREADS, GEMM_SMEM>>>(
            xh, mb, bias2, qv, nullptr, nullptr, nullptr,
            MS, N2, FDIM, FDIM, FDIM, N2, 0, 0, 0, 1.0f, 1, 0);
    }

    // 2) sc = exp((qm x^T + u + v) / sqrt(dk)), plus column partial sums
    {
        dim3 grd(SEQ / BN, SEQ / BM, BATCH);
        gemm_f16_kernel<<<grd, GEMM_THREADS, GEMM_SMEM>>>(
            qv, xh, nullptr, sc, part, u, v,
            SEQ, SEQ, DKDIM, N2, FDIM, SEQ,
            sQV, sXF, sSS, inv_sqrt_dk, 1, 1);
    }

    // 3) vw^T with VSCALE/colsum folded in
    {
        dim3 blk(32, 8);
        dim3 g(DKDIM / 32, SEQ / 32, BATCH);
        transpose_scale_kernel<<<g, blk>>>(qv + DKDIM, vwt, part,
                                           SEQ, DKDIM, N2, sQV, (long long)FDIM * SEQ);
    }

    // 4) out = (1/VSCALE) * sc @ vwt^T + bo   (fp32 out; folds ctx@Wo)
    {
        dim3 grd(FDIM / BN, SEQ / BM, BATCH);
        gemm_f16_kernel<<<grd, GEMM_THREADS, GEMM_SMEM>>>(
            sc, vwt, bo, out, nullptr, nullptr, nullptr,
            SEQ, FDIM, SEQ, SEQ, SEQ, FDIM,
            sSS, (long long)FDIM * SEQ, sXF, 1.0f / VSCALE, 0, 0);
    }
}

// round 12
// speedup vs baseline: 1.5271x; 1.5271x over previous
#include <cuda_runtime.h>
#include <cuda_fp16.h>
#include <cstdint>
#include <math.h>

// ---------------------------------------------------------------------------
// Problem constants
// ---------------------------------------------------------------------------
#define BATCH 4
#define SEQ   2048
#define FDIM  1024
#define DKDIM 1024

// ---------------------------------------------------------------------------
// fp16 mma.sync GEMM tiling: CTA 128x128, warp 64x32, BK=64, 3 stages, 2 CTA/SM
// ---------------------------------------------------------------------------
#define BM 128
#define BN 128
#define BK 64
#define STAGES 3
#define GEMM_THREADS 256

#define ROWH 72
#define A_STAGE_HALVES (BM * ROWH)
#define B_STAGE_HALVES (BN * ROWH)
#define STAGE_HALVES   (A_STAGE_HALVES + B_STAGE_HALVES)
#define GEMM_SMEM      (STAGES * STAGE_HALVES * 2)   // 110,592 B

#define VSCALE 64.0f
#define MTILES (SEQ / BM)

// ---------------------------------------------------------------------------
// Scratch (device globals — no dynamic allocation allowed)
// ---------------------------------------------------------------------------
__device__ __half g_xh  [(size_t)BATCH * SEQ * FDIM];
__device__ __half g_gA  [(size_t)2 * FDIM * DKDIM];          // slot0: Wk, slot1: Wo^T
__device__ __half g_gB  [(size_t)2 * FDIM * DKDIM];          // slot0: Wq, slot1: Wv
__device__ __half g_mb  [(size_t)2 * DKDIM * FDIM];          // slot0: M'=WkWq^T, slot1: W'^T
__device__ __half g_qv  [(size_t)BATCH * SEQ * 2 * DKDIM];   // [qm | vw] in N
__device__ __half g_vwt [(size_t)BATCH * FDIM * SEQ];        // scaled vw^T per batch
__device__ __half g_sc  [(size_t)BATCH * SEQ * SEQ];         // exp(scores)
__device__ float  g_bias2[(size_t)2 * DKDIM];                // 0 | b'=bv@Wo
__device__ float  g_w1  [FDIM];                              // Wq @ bk
__device__ float  g_w2  [FDIM];                              // Wk @ bq
__device__ float  g_c   [1];                                 // bq . bk
__device__ float  g_u   [(size_t)BATCH * SEQ];               // x.w1 + c
__device__ float  g_v   [(size_t)BATCH * SEQ];               // x.w2
__device__ float  g_part[(size_t)BATCH * MTILES * SEQ];

// ---------------------------------------------------------------------------
// Helpers
// ---------------------------------------------------------------------------
__device__ __forceinline__ uint32_t smem_u32(const void* p) {
    uint32_t a;
    asm("{ .reg .u64 t; cvta.to.shared.u64 t, %1; cvt.u32.u64 %0, t; }" : "=r"(a) : "l"(p));
    return a;
}
__device__ __forceinline__ void cp_async16(uint32_t dst, const void* src) {
    asm volatile("cp.async.cg.shared.global [%0], [%1], 16;" :: "r"(dst), "l"(src) : "memory");
}
__device__ __forceinline__ void cp_commit() {
    asm volatile("cp.async.commit_group;" ::: "memory");
}
__device__ __forceinline__ void cp_wait_1() {
    asm volatile("cp.async.wait_group 1;" ::: "memory");
}
__device__ __forceinline__ void ldmatrix_x4(uint32_t* r, uint32_t addr) {
    asm volatile("ldmatrix.sync.aligned.m8n8.x4.shared.b16 {%0,%1,%2,%3}, [%4];"
                 : "=r"(r[0]), "=r"(r[1]), "=r"(r[2]), "=r"(r[3]) : "r"(addr));
}
__device__ __forceinline__ void mma_f16(float* d, const uint32_t* a,
                                        uint32_t b0, uint32_t b1) {
    asm volatile(
        "mma.sync.aligned.m16n8k16.row.col.f32.f16.f16.f32 "
        "{%0,%1,%2,%3}, {%4,%5,%6,%7}, {%8,%9}, {%0,%1,%2,%3};"
        : "+f"(d[0]), "+f"(d[1]), "+f"(d[2]), "+f"(d[3])
        : "r"(a[0]), "r"(a[1]), "r"(a[2]), "r"(a[3]), "r"(b0), "r"(b1));
}

// ---------------------------------------------------------------------------
// fp16 tensor-core GEMM:  C = op(alpha * A * B^T + bias)
//   mode 0: plain; mode 1: C = exp((acc + u_m + v_n) * alpha), col sums -> part
// ---------------------------------------------------------------------------
__global__ void __launch_bounds__(GEMM_THREADS, 2)
gemm_f16_kernel(const __half* __restrict__ A, const __half* __restrict__ B,
                const float* __restrict__ bias, void* __restrict__ Cv,
                float* __restrict__ part,
                const float* __restrict__ upt, const float* __restrict__ vpt,
                int M, int N, int K, int lda, int ldb, int ldc,
                long long sA, long long sB, long long sC,
                float alpha, int c_half, int mode)
{
    extern __shared__ __half sm[];
    __shared__ float csum[2][BN];
    const int tid = threadIdx.x;
    const int wid = tid >> 5;
    const int lane = tid & 31;
    const int g   = lane >> 2;
    const int tig = lane & 3;
    const int mw = (wid & 1) * 64;
    const int nw = (wid >> 1) * 32;

    A += (long long)blockIdx.z * sA;
    B += (long long)blockIdx.z * sB;
    const int m0 = blockIdx.y * BM;
    const int n0 = blockIdx.x * BN;

    float acc[4][4][4];
#pragma unroll
    for (int mt = 0; mt < 4; mt++)
#pragma unroll
        for (int nt = 0; nt < 4; nt++)
#pragma unroll
            for (int r = 0; r < 4; r++) acc[mt][nt][r] = 0.0f;

    const uint32_t sm_base = smem_u32(sm);
    const int KT = K / BK;

    auto load_stage = [&](int p) {
        const uint32_t base = sm_base + (uint32_t)((p % STAGES) * STAGE_HALVES) * 2u;
        const uint32_t bbase = base + A_STAGE_HALVES * 2u;
        const int k0 = p * BK;
#pragma unroll
        for (int t = 0; t < 4; t++) {
            int c = tid + t * GEMM_THREADS;
            int r = c >> 3, kc = c & 7;
            cp_async16(base + (uint32_t)(r * ROWH + kc * 8) * 2u,
                       A + (long long)(m0 + r) * lda + k0 + kc * 8);
        }
#pragma unroll
        for (int t = 0; t < 4; t++) {
            int c = tid + t * GEMM_THREADS;
            int r = c >> 3, kc = c & 7;
            cp_async16(bbase + (uint32_t)(r * ROWH + kc * 8) * 2u,
                       B + (long long)(n0 + r) * ldb + k0 + kc * 8);
        }
    };

    load_stage(0); cp_commit();
    load_stage(1); cp_commit();

    const int row_a  = ((lane >> 3) & 1) * 8 + (lane & 7);
    const int kadd_a = ((lane >> 4) & 1) * 8;
    const int row_b  = ((lane >> 4) & 1) * 8 + (lane & 7);
    const int kadd_b = ((lane >> 3) & 1) * 8;

    for (int kt = 0; kt < KT; kt++) {
        cp_wait_1();
        __syncthreads();

        if (kt + 2 < KT) load_stage(kt + 2);
        cp_commit();

        const uint32_t sa  = sm_base + (uint32_t)((kt % STAGES) * STAGE_HALVES) * 2u;
        const uint32_t sbp = sa + A_STAGE_HALVES * 2u;
#pragma unroll
        for (int kk = 0; kk < 4; kk++) {
            const int k16 = kk * 16;
            uint32_t a[4][4], b[2][4];
#pragma unroll
            for (int mt = 0; mt < 4; mt++)
                ldmatrix_x4(a[mt],
                    sa + (uint32_t)((mw + mt * 16 + row_a) * ROWH + k16 + kadd_a) * 2u);
#pragma unroll
            for (int i = 0; i < 2; i++)
                ldmatrix_x4(b[i],
                    sbp + (uint32_t)((nw + i * 16 + row_b) * ROWH + k16 + kadd_b) * 2u);
#pragma unroll
            for (int mt = 0; mt < 4; mt++)
#pragma unroll
                for (int nt = 0; nt < 4; nt++)
                    mma_f16(acc[mt][nt], a[mt],
                            b[nt >> 1][(nt & 1) * 2], b[nt >> 1][(nt & 1) * 2 + 1]);
        }
    }

    if (mode == 1) {
        // ---- exp((acc + u_m + v_n) * alpha) epilogue + column partial sums ----
        __half* C = (__half*)Cv + (long long)blockIdx.z * sC;
        const float* u_ = upt + (long long)blockIdx.z * SEQ;
        const float* v_ = vpt + (long long)blockIdx.z * SEQ;
        float vn0[4], vn1[4];
#pragma unroll
        for (int nt = 0; nt < 4; nt++) {
            const int n = n0 + nw + nt * 8 + 2 * tig;
            vn0[nt] = v_[n];
            vn1[nt] = v_[n + 1];
        }
        float cs0[4], cs1[4];
#pragma unroll
        for (int nt = 0; nt < 4; nt++) { cs0[nt] = 0.0f; cs1[nt] = 0.0f; }
#pragma unroll
        for (int mt = 0; mt < 4; mt++) {
            const int m = m0 + mw + mt * 16 + g;
            const float um0 = u_[m], um8 = u_[m + 8];
#pragma unroll
            for (int nt = 0; nt < 4; nt++) {
                const int n = n0 + nw + nt * 8 + 2 * tig;
                float e0 = __expf((acc[mt][nt][0] + um0 + vn0[nt]) * alpha);
                float e1 = __expf((acc[mt][nt][1] + um0 + vn1[nt]) * alpha);
                float e2 = __expf((acc[mt][nt][2] + um8 + vn0[nt]) * alpha);
                float e3 = __expf((acc[mt][nt][3] + um8 + vn1[nt]) * alpha);
                cs0[nt] += e0 + e2;
                cs1[nt] += e1 + e3;
                *(__half2*)(C + (long long)m * ldc + n)       = __floats2half2_rn(e0, e1);
                *(__half2*)(C + (long long)(m + 8) * ldc + n) = __floats2half2_rn(e2, e3);
            }
        }
#pragma unroll
        for (int msk = 4; msk <= 16; msk <<= 1) {
#pragma unroll
            for (int nt = 0; nt < 4; nt++) {
                cs0[nt] += __shfl_xor_sync(0xffffffffu, cs0[nt], msk);
                cs1[nt] += __shfl_xor_sync(0xffffffffu, cs1[nt], msk);
            }
        }
        if (g == 0) {
#pragma unroll
            for (int nt = 0; nt < 4; nt++) {
                csum[wid & 1][nw + nt * 8 + 2 * tig]     = cs0[nt];
                csum[wid & 1][nw + nt * 8 + 2 * tig + 1] = cs1[nt];
            }
        }
        __syncthreads();
        if (tid < BN)
            part[((long long)blockIdx.z * MTILES + blockIdx.y) * SEQ + n0 + tid] =
                csum[0][tid] + csum[1][tid];
        return;
    }

    // ---- plain epilogue ----
#pragma unroll
    for (int mt = 0; mt < 4; mt++) {
        const int m = m0 + mw + mt * 16 + g;
#pragma unroll
        for (int nt = 0; nt < 4; nt++) {
            const int n = n0 + nw + nt * 8 + 2 * tig;
            float2 v0, v1;
            v0.x = acc[mt][nt][0] * alpha;
            v0.y = acc[mt][nt][1] * alpha;
            v1.x = acc[mt][nt][2] * alpha;
            v1.y = acc[mt][nt][3] * alpha;
            if (bias) {
                float bx = bias[n], by = bias[n + 1];
                v0.x += bx; v0.y += by;
                v1.x += bx; v1.y += by;
            }
            if (c_half) {
                __half* C = (__half*)Cv + (long long)blockIdx.z * sC;
                *(__half2*)(C + (long long)m * ldc + n)       = __floats2half2_rn(v0.x, v0.y);
                *(__half2*)(C + (long long)(m + 8) * ldc + n) = __floats2half2_rn(v1.x, v1.y);
            } else {
                float* C = (float*)Cv + (long long)blockIdx.z * sC;
                *(float2*)(C + (long long)m * ldc + n)       = v0;
                *(float2*)(C + (long long)(m + 8) * ldc + n) = v1;
            }
        }
    }
}

// ---------------------------------------------------------------------------
// Fused prep. 1D grid dispatch (256 threads each) — SMALL latency-bound blocks
// FIRST so they hide under the 12K-block bulk instead of forming a serial tail:
// [0,4)          b' = bv@Wo -> bias2[1024:2048]  (8-way unrolled, MLP)
// [4,132)        w1 = Wq@bk   (warp per row, coalesced)
// [132,260)      w2 = Wk@bq   (warp per row, coalesced)
// [260,264)      bias2[0:1024] = 0
// [264]          c = bq.bk
// [265,8457)     x f2h
// [8457,11529)   Wq/Wk/Wv f2h -> gB0/gA0/gB1
// [11529,12553)  Wo transpose -> gA slot1 (Wo^T)
// ---------------------------------------------------------------------------
__global__ void __launch_bounds__(256)
prep_kernel(const float* __restrict__ x,
            const float* __restrict__ Wq, const float* __restrict__ Wk,
            const float* __restrict__ Wv, const float* __restrict__ Wo,
            const float* __restrict__ bq, const float* __restrict__ bk,
            const float* __restrict__ bv,
            __half* __restrict__ xh, __half* __restrict__ gA,
            __half* __restrict__ gB, float* __restrict__ bias2,
            float* __restrict__ w1, float* __restrict__ w2,
            float* __restrict__ cc)
{
    __shared__ float t[32][33];
    const int b = blockIdx.x;
    const int tid = threadIdx.x;
    const int tx = tid & 31, ty = tid >> 5;

    if (b < 4) {
        // b'[f] = sum_d bv[d] * Wo[d,f]; 8 independent partial sums for MLP
        const int f = b * 256 + tid;
        float s0 = 0.f, s1 = 0.f, s2 = 0.f, s3 = 0.f;
        float s4 = 0.f, s5 = 0.f, s6 = 0.f, s7 = 0.f;
        for (int d = 0; d < DKDIM; d += 8) {
            s0 += bv[d + 0] * Wo[(long long)(d + 0) * FDIM + f];
            s1 += bv[d + 1] * Wo[(long long)(d + 1) * FDIM + f];
            s2 += bv[d + 2] * Wo[(long long)(d + 2) * FDIM + f];
            s3 += bv[d + 3] * Wo[(long long)(d + 3) * FDIM + f];
            s4 += bv[d + 4] * Wo[(long long)(d + 4) * FDIM + f];
            s5 += bv[d + 5] * Wo[(long long)(d + 5) * FDIM + f];
            s6 += bv[d + 6] * Wo[(long long)(d + 6) * FDIM + f];
            s7 += bv[d + 7] * Wo[(long long)(d + 7) * FDIM + f];
        }
        bias2[DKDIM + f] = ((s0 + s1) + (s2 + s3)) + ((s4 + s5) + (s6 + s7));
    } else if (b < 260) {
        // w1 / w2: one warp per output row, lanes over d (coalesced)
        const int is_w2 = (b >= 132);
        const int f = ((b - (is_w2 ? 132 : 4)) << 3) + ty;   // 8 warps/block
        const float* row = (is_w2 ? Wk : Wq) + (long long)f * DKDIM;
        const float* bb = is_w2 ? bq : bk;
        float s = 0.0f;
#pragma unroll
        for (int j = 0; j < DKDIM / 32; j++)
            s += row[tx + j * 32] * bb[tx + j * 32];
#pragma unroll
        for (int msk = 16; msk > 0; msk >>= 1)
            s += __shfl_xor_sync(0xffffffffu, s, msk);
        if (tx == 0) (is_w2 ? w2 : w1)[f] = s;
    } else if (b < 264) {
        bias2[(b - 260) * 256 + tid] = 0.0f;
    } else if (b == 264) {
        __shared__ float red[256];
        float s = 0.0f;
        for (int d = tid; d < DKDIM; d += 256) s += bq[d] * bk[d];
        red[tid] = s;
        __syncthreads();
        for (int off = 128; off > 0; off >>= 1) {
            if (tid < off) red[tid] += red[tid + off];
            __syncthreads();
        }
        if (tid == 0) cc[0] = red[0];
    } else if (b < 8457) {
        size_t i = (size_t)(b - 265) * 256 + tid;
        float4 v = ((const float4*)x)[i];
        ((__half2*)xh)[2 * i]     = __floats2half2_rn(v.x, v.y);
        ((__half2*)xh)[2 * i + 1] = __floats2half2_rn(v.z, v.w);
    } else if (b < 11529) {
        const int z = (b - 8457) >> 10;                 // 0: Wq, 1: Wk, 2: Wv
        const float* in = (z == 0) ? Wq : (z == 1) ? Wk : Wv;
        __half* o = (z == 0) ? gB : (z == 1) ? gA : (gB + (size_t)FDIM * DKDIM);
        size_t i = (size_t)((b - 8457) & 1023) * 256 + tid;
        float4 v = ((const float4*)in)[i];
        ((__half2*)o)[2 * i]     = __floats2half2_rn(v.x, v.y);
        ((__half2*)o)[2 * i + 1] = __floats2half2_rn(v.z, v.w);
    } else {
        // Wo [DK,F] -> Wo^T [F,DK] into gA slot1
        const int tt = b - 11529;
        const int by = tt >> 5, bx = tt & 31;
        const int c0 = bx * 32, r0 = by * 32;
        __half* o = gA + (size_t)FDIM * DKDIM;
#pragma unroll
        for (int i = 0; i < 32; i += 8)
            t[ty + i][tx] = Wo[(long long)(r0 + ty + i) * FDIM + c0 + tx];
        __syncthreads();
#pragma unroll
        for (int i = 0; i < 32; i += 8)
            o[(long long)(c0 + ty + i) * DKDIM + r0 + tx] =
                __float2half_rn(t[tx][ty + i]);
    }
}

// ---------------------------------------------------------------------------
// u[i] = x[i].w1 + c ; v[i] = x[i].w2   (one warp per row)
// ---------------------------------------------------------------------------
__global__ void __launch_bounds__(256)
uv_kernel(const float* __restrict__ x, const float* __restrict__ w1,
          const float* __restrict__ w2, const float* __restrict__ cc,
          float* __restrict__ u, float* __restrict__ v)
{
    const int lane = threadIdx.x & 31;
    const int w = threadIdx.x >> 5;
    const long long i = (long long)blockIdx.x * 8 + w;
    const float* row = x + i * FDIM;
    float s1 = 0.0f, s2 = 0.0f;
#pragma unroll
    for (int j = 0; j < FDIM / 32; j++) {
        float xv = row[lane + j * 32];
        s1 += xv * w1[lane + j * 32];
        s2 += xv * w2[lane + j * 32];
    }
#pragma unroll
    for (int msk = 16; msk > 0; msk >>= 1) {
        s1 += __shfl_xor_sync(0xffffffffu, s1, msk);
        s2 += __shfl_xor_sync(0xffffffffu, s2, msk);
    }
    if (lane == 0) { u[i] = s1 + cc[0]; v[i] = s2; }
}

// ---------------------------------------------------------------------------
// vw^T with softmax normalization folded in (colsum reduced inline from part)
// out[f, k] = vw[k, f] * VSCALE / colsum[b, k]
// ---------------------------------------------------------------------------
__global__ void __launch_bounds__(256)
transpose_scale_kernel(const __half* __restrict__ in, __half* __restrict__ out,
                       const float* __restrict__ part,
                       int R, int C, int ldIn, long long sIn, long long sOut)
{
    __shared__ __half t[32][34];
    in  += (long long)blockIdx.z * sIn;
    out += (long long)blockIdx.z * sOut;
    const int c0 = blockIdx.x * 32, r0 = blockIdx.y * 32;
#pragma unroll
    for (int i = 0; i < 32; i += 8)
        t[threadIdx.y + i][threadIdx.x] =
            in[(long long)(r0 + threadIdx.y + i) * ldIn + c0 + threadIdx.x];
    __syncthreads();
    const float* pp = part + (long long)blockIdx.z * MTILES * SEQ + r0 + threadIdx.x;
    float s = 0.0f;
#pragma unroll
    for (int tt = 0; tt < MTILES; tt++) s += pp[(long long)tt * SEQ];
    const float inv = VSCALE / s;
#pragma unroll
    for (int i = 0; i < 32; i += 8)
        out[(long long)(c0 + threadIdx.y + i) * R + r0 + threadIdx.x] =
            __float2half_rn(__half2float(t[threadIdx.x][threadIdx.y + i]) * inv);
}

// ---------------------------------------------------------------------------
// Launcher
// ---------------------------------------------------------------------------
extern "C" void kernel_launch(void* const* d_in, const int* in_sizes, int n_in,
                              void* d_out, int out_size)
{
    const float* x  = (const float*)d_in[0];
    const float* Wq = (const float*)d_in[1];
    const float* bq = (const float*)d_in[2];
    const float* Wk = (const float*)d_in[3];
    const float* bk = (const float*)d_in[4];
    const float* Wv = (const float*)d_in[5];
    const float* bv = (const float*)d_in[6];
    const float* Wo = (const float*)d_in[7];
    const float* bo = (const float*)d_in[8];
    float* out = (float*)d_out;

    __half *xh, *gA, *gB, *mb, *qv, *vwt, *sc;
    float *bias2, *w1, *w2, *cc, *u, *v, *part;
    cudaGetSymbolAddress((void**)&xh,    g_xh);
    cudaGetSymbolAddress((void**)&gA,    g_gA);
    cudaGetSymbolAddress((void**)&gB,    g_gB);
    cudaGetSymbolAddress((void**)&mb,    g_mb);
    cudaGetSymbolAddress((void**)&qv,    g_qv);
    cudaGetSymbolAddress((void**)&vwt,   g_vwt);
    cudaGetSymbolAddress((void**)&sc,    g_sc);
    cudaGetSymbolAddress((void**)&bias2, g_bias2);
    cudaGetSymbolAddress((void**)&w1,    g_w1);
    cudaGetSymbolAddress((void**)&w2,    g_w2);
    cudaGetSymbolAddress((void**)&cc,    g_c);
    cudaGetSymbolAddress((void**)&u,     g_u);
    cudaGetSymbolAddress((void**)&v,     g_v);
    cudaGetSymbolAddress((void**)&part,  g_part);

    cudaFuncSetAttribute(gemm_f16_kernel,
                         cudaFuncAttributeMaxDynamicSharedMemorySize, GEMM_SMEM);

    const int MS = BATCH * SEQ;                        // 8192
    const int N2 = 2 * DKDIM;                          // 2048
    const long long sQV = (long long)SEQ * N2;
    const long long sXF = (long long)SEQ * FDIM;
    const long long sSS = (long long)SEQ * SEQ;
    const long long sW  = (long long)FDIM * DKDIM;
    const float inv_sqrt_dk = 1.0f / 32.0f;

    // 0) fused prep (small latency-bound blocks FIRST, hidden under bulk)
    prep_kernel<<<12553, 256>>>(x, Wq, Wk, Wv, Wo, bq, bk, bv,
                                xh, gA, gB, bias2, w1, w2, cc);

    // 0b) batched prep GEMM: z=0: M' = Wk@Wq^T ; z=1: W'^T = Wo^T@Wv^T
    {
        dim3 grd(FDIM / BN, FDIM / BM, 2);
        gemm_f16_kernel<<<grd, GEMM_THREADS, GEMM_SMEM>>>(
            gA, gB, nullptr, mb, nullptr, nullptr, nullptr,
            FDIM, FDIM, DKDIM, DKDIM, DKDIM, FDIM, sW, sW, sW, 1.0f, 1, 0);
    }

    // 0c) u, v rank-1 score terms
    uv_kernel<<<MS / 8, 256>>>(x, w1, w2, cc, u, v);

    // 1) fused [qm | vw] = xh @ [M' | W'^T]^T + [0 | b']  (half out)
    {
        dim3 grd(N2 / BN, MS / BM, 1);
        gemm_f16_kernel<<<grd, GEMM_THREADS, GEMM_SMEM>>>(
            xh, mb, bias2, qv, nullptr, nullptr, nullptr,
            MS, N2, FDIM, FDIM, FDIM, N2, 0, 0, 0, 1.0f, 1, 0);
    }

    // 2) sc = exp((qm x^T + u + v) / sqrt(dk)), plus column partial sums
    {
        dim3 grd(SEQ / BN, SEQ / BM, BATCH);
        gemm_f16_kernel<<<grd, GEMM_THREADS, GEMM_SMEM>>>(
            qv, xh, nullptr, sc, part, u, v,
            SEQ, SEQ, DKDIM, N2, FDIM, SEQ,
            sQV, sXF, sSS, inv_sqrt_dk, 1, 1);
    }

    // 3) vw^T with VSCALE/colsum folded in
    {
        dim3 blk(32, 8);
        dim3 g(DKDIM / 32, SEQ / 32, BATCH);
        transpose_scale_kernel<<<g, blk>>>(qv + DKDIM, vwt, part,
                                           SEQ, DKDIM, N2, sQV, (long long)FDIM * SEQ);
    }

    // 4) out = (1/VSCALE) * sc @ vwt^T + bo   (fp32 out; folds ctx@Wo)
    {
        dim3 grd(FDIM / BN, SEQ / BM, BATCH);
        gemm_f16_kernel<<<grd, GEMM_THREADS, GEMM_SMEM>>>(
            sc, vwt, bo, out, nullptr, nullptr, nullptr,
            SEQ, FDIM, SEQ, SEQ, SEQ, FDIM,
            sSS, (long long)FDIM * SEQ, sXF, 1.0f / VSCALE, 0, 0);
    }
}